// round 11
// baseline (speedup 1.0000x reference)
#include <cuda_runtime.h>
#include <cuda_bf16.h>
#include <cstdint>

#define LSEQ 2048
typedef unsigned long long ull;

__device__ float g_ctx_scratch[2 * 16 * 2048 * 64];

// ---- smem layout (operand pitch 72 bf16 = 144B rows) ----
#define OKH 0
#define OKL 18432
#define OEH 36864
#define OEL 55296
#define ORS 73728
#define RSPITCH 260
#define SMEM_TOT (73728 + 128 * RSPITCH * 4)   // 206848
// pv phase reuses: OKH/OKL = V hi/lo, OEH = iz[128]

__device__ __forceinline__ uint32_t smem_u32(const void* p) {
    uint32_t a;
    asm("{ .reg .u64 t; cvta.to.shared.u64 t, %1; cvt.u32.u64 %0, t; }" : "=r"(a) : "l"(p));
    return a;
}
__device__ __forceinline__ void ldmA(uint32_t* a, uint32_t addr) {
    asm volatile("ldmatrix.sync.aligned.m8n8.x4.shared.b16 {%0,%1,%2,%3}, [%4];"
        : "=r"(a[0]), "=r"(a[1]), "=r"(a[2]), "=r"(a[3]) : "r"(addr));
}
__device__ __forceinline__ void ldmB(uint32_t* b, uint32_t addr) {
    asm volatile("ldmatrix.sync.aligned.m8n8.x2.shared.b16 {%0,%1}, [%2];"
        : "=r"(b[0]), "=r"(b[1]) : "r"(addr));
}
__device__ __forceinline__ void ldmBT(uint32_t* b, uint32_t addr) {
    asm volatile("ldmatrix.sync.aligned.m8n8.x2.trans.shared.b16 {%0,%1}, [%2];"
        : "=r"(b[0]), "=r"(b[1]) : "r"(addr));
}
__device__ __forceinline__ void mmabf(float* d, const uint32_t* a, const uint32_t* b) {
    asm volatile("mma.sync.aligned.m16n8k16.row.col.f32.bf16.bf16.f32 "
        "{%0,%1,%2,%3}, {%4,%5,%6,%7}, {%8,%9}, {%0,%1,%2,%3};"
        : "+f"(d[0]), "+f"(d[1]), "+f"(d[2]), "+f"(d[3])
        : "r"(a[0]), "r"(a[1]), "r"(a[2]), "r"(a[3]), "r"(b[0]), "r"(b[1]));
}
__device__ __forceinline__ uint32_t pkbf(float a, float b) {
    __nv_bfloat162 h = __floats2bfloat162_rn(a, b);
    return *(uint32_t*)&h;
}
__device__ __forceinline__ void split72(char* hi, char* lo, int r, int c4, float4 v) {
    float hx = __bfloat162float(__float2bfloat16(v.x));
    float hy = __bfloat162float(__float2bfloat16(v.y));
    float hz = __bfloat162float(__float2bfloat16(v.z));
    float hw = __bfloat162float(__float2bfloat16(v.w));
    int off = r * 144 + c4 * 8;
    *(uint2*)(hi + off) = make_uint2(pkbf(v.x, v.y), pkbf(v.z, v.w));
    *(uint2*)(lo + off) = make_uint2(pkbf(v.x - hx, v.y - hy), pkbf(v.z - hz, v.w - hw));
}

// ================== fused scores + softmax + PV ==================
__global__ void __launch_bounds__(256, 1)
fused_attn(const float* __restrict__ Q, const float* __restrict__ K,
           const float* __restrict__ Er, const float* __restrict__ V,
           float* __restrict__ ctx, float* __restrict__ attn)
{
    extern __shared__ char sm[];
    const uint32_t sb = smem_u32(sm);
    float* Rs = (float*)(sm + ORS);

    const int qt = 15 - (int)blockIdx.x;
    const int bh = blockIdx.y;
    const int q0 = qt * 128;
    const int t = threadIdx.x;
    const int wid = t >> 5, lane = t & 31;
    const int wm = wid >> 1, wn = wid & 1;

    if (ctx == nullptr) ctx = g_ctx_scratch;
    const float* Qg = Q + (size_t)bh * LSEQ * 64;
    const float* Kg = K + (size_t)bh * LSEQ * 64;
    const float* Vg = V + (size_t)bh * LSEQ * 64;
    float* attng = attn + (size_t)bh * LSEQ * LSEQ;
    float* ctxg = ctx + (size_t)bh * LSEQ * 64;

    // ---------------- Phase 1: scores ----------------
    // stage Q in ring region (reused after fragments are in regs)
    for (int i = t; i < 2048; i += 256) {
        int r = i >> 4, c4 = i & 15;
        split72(sm + ORS, sm + ORS + 18432, r, c4,
                *((const float4*)(Qg + (size_t)(q0 + r) * 64 + 4 * c4)));
    }
    __syncthreads();

    const int arow = (lane & 7) + 8 * ((lane >> 3) & 1);
    const int acolB = 16 * (lane >> 4);
    uint32_t AH[2][4][4], AL[2][4][4];
#pragma unroll
    for (int mt = 0; mt < 2; mt++)
#pragma unroll
        for (int ks = 0; ks < 4; ks++) {
            uint32_t ro = (uint32_t)((32 * wm + 16 * mt + arow) * 144 + ks * 32 + acolB);
            ldmA(AH[mt][ks], sb + ORS + ro);
            ldmA(AL[mt][ks], sb + ORS + 18432 + ro);
        }

    const int browB = (lane & 7) * 144;
    const int bcolB = 16 * ((lane >> 3) & 1);
    float zacc[2][2] = {{0.f, 0.f}, {0.f, 0.f}};

    const int lr = t >> 4, lc4 = t & 15;

    // prefetch tile h=0
    float4 kb[8], eb[8];
    {
        const int k0 = qt * 128;
#pragma unroll
        for (int jj = 0; jj < 8; jj++)
            kb[jj] = *((const float4*)(Kg + (size_t)(k0 + lr + 16 * jj) * 64 + 4 * lc4));
#pragma unroll
        for (int jj = 0; jj < 8; jj++)
            eb[jj] = *((const float4*)(Er + (size_t)(2047 - (lr + 16 * jj)) * 64 + 4 * lc4));
    }

    for (int h = 0; h <= qt; h++) {
        const int k0 = (qt - h) * 128;
        __syncthreads();

#pragma unroll
        for (int jj = 0; jj < 8; jj++)
            split72(sm + OKH, sm + OKL, lr + 16 * jj, lc4, kb[jj]);
#pragma unroll
        for (int jj = 0; jj < 8; jj++)
            split72(sm + OEH, sm + OEL, lr + 16 * jj, lc4, eb[jj]);

        if (h < qt) {
            const int k0n = (qt - h - 1) * 128;
            const int ebn = 2047 - 128 * (h + 1);
#pragma unroll
            for (int jj = 0; jj < 8; jj++)
                kb[jj] = *((const float4*)(Kg + (size_t)(k0n + lr + 16 * jj) * 64 + 4 * lc4));
#pragma unroll
            for (int jj = 0; jj < 8; jj++)
                eb[jj] = *((const float4*)(Er + (size_t)(ebn - (lr + 16 * jj)) * 64 + 4 * lc4));
        }
        __syncthreads();

        // R phase: 128 new cols (block D_{h+1}) -> ring slot (h+1)&1
        const int slotW = 128 * ((h + 1) & 1);
#pragma unroll 1
        for (int nt = 0; nt < 8; nt++) {
            float racc[2][4] = {{0.f, 0.f, 0.f, 0.f}, {0.f, 0.f, 0.f, 0.f}};
            const uint32_t nb = (uint32_t)((64 * wn + 8 * nt) * 144) + browB + bcolB;
#pragma unroll
            for (int ks = 0; ks < 4; ks++) {
                uint32_t BH[2], BL[2];
                ldmB(BH, sb + OEH + nb + ks * 32);
                ldmB(BL, sb + OEL + nb + ks * 32);
#pragma unroll
                for (int mt = 0; mt < 2; mt++) {
                    mmabf(racc[mt], AH[mt][ks], BH);
                    mmabf(racc[mt], AH[mt][ks], BL);
                    mmabf(racc[mt], AL[mt][ks], BH);
                }
            }
            const int c = slotW + 64 * wn + 8 * nt + 2 * (lane & 3);
#pragma unroll
            for (int mt = 0; mt < 2; mt++) {
                int q = 32 * wm + 16 * mt + (lane >> 2);
                *((float2*)(Rs + q * RSPITCH + c)) = make_float2(racc[mt][0], racc[mt][1]);
                *((float2*)(Rs + (q + 8) * RSPITCH + c)) = make_float2(racc[mt][2], racc[mt][3]);
            }
        }
        __syncthreads();

        // S + epilogue over two 64-col halves
        const int sA = 128 * ((h + 1) & 1);
        const int sB = 128 * (h & 1);
        const bool diag = (h == 0);
#pragma unroll 1
        for (int kh = 0; kh < 2; kh++) {
            float sacc[2][4][4];
#pragma unroll
            for (int mt = 0; mt < 2; mt++)
#pragma unroll
                for (int nt = 0; nt < 4; nt++)
#pragma unroll
                    for (int r = 0; r < 4; r++) sacc[mt][nt][r] = 0.f;
#pragma unroll
            for (int nt = 0; nt < 4; nt++) {
                const uint32_t nb = (uint32_t)((64 * kh + 32 * wn + 8 * nt) * 144) + browB + bcolB;
#pragma unroll
                for (int ks = 0; ks < 4; ks++) {
                    uint32_t BH[2], BL[2];
                    ldmB(BH, sb + OKH + nb + ks * 32);
                    ldmB(BL, sb + OKL + nb + ks * 32);
#pragma unroll
                    for (int mt = 0; mt < 2; mt++) {
                        mmabf(sacc[mt][nt], AH[mt][ks], BH);
                        mmabf(sacc[mt][nt], AH[mt][ks], BL);
                        mmabf(sacc[mt][nt], AL[mt][ks], BH);
                    }
                }
            }
#pragma unroll
            for (int mt = 0; mt < 2; mt++) {
#pragma unroll
                for (int nt = 0; nt < 4; nt++) {
                    const int klocal = 64 * kh + 32 * wn + 8 * nt + 2 * (lane & 3);
                    const int kg = k0 + klocal;
#pragma unroll
                    for (int rh = 0; rh < 2; rh++) {
                        const int r = 32 * wm + 16 * mt + 8 * rh + (lane >> 2);
                        const int qg = q0 + r;
                        const int d0 = r - klocal;
                        const int d1 = d0 - 1;
                        float r0 = Rs[r * RSPITCH + ((d0 & 127) + (d0 >= 0 ? sA : sB))];
                        float r1 = Rs[r * RSPITCH + ((d1 & 127) + (d1 >= 0 ? sA : sB))];
                        float s0 = (sacc[mt][nt][2 * rh] + r0) * 0.125f;
                        float s1 = (sacc[mt][nt][2 * rh + 1] + r1) * 0.125f;
                        float p0 = __expf(s0), p1 = __expf(s1);
                        if (diag) {
                            if (kg > qg) p0 = 0.f;
                            if (kg + 1 > qg) p1 = 0.f;
                        }
                        zacc[mt][rh] += p0 + p1;
                        *((float2*)(attng + (size_t)qg * LSEQ + kg)) = make_float2(p0, p1);
                    }
                }
            }
        }
    }

    // ---- z reduce -> smem iz (at OEH, free in pv phase) ----
    float* smIZ = (float*)(sm + OEH);
#pragma unroll
    for (int mt = 0; mt < 2; mt++)
#pragma unroll
        for (int rh = 0; rh < 2; rh++) {
            float v = zacc[mt][rh];
            v += __shfl_xor_sync(0xffffffffu, v, 1);
            v += __shfl_xor_sync(0xffffffffu, v, 2);
            zacc[mt][rh] = v;
        }
    __syncthreads();
    float* zb = Rs;
    if ((lane & 3) == 0) {
#pragma unroll
        for (int mt = 0; mt < 2; mt++)
#pragma unroll
            for (int rh = 0; rh < 2; rh++) {
                int row = 32 * wm + 16 * mt + 8 * rh + (lane >> 2);
                zb[row * 2 + wn] = zacc[mt][rh];
            }
    }
    __syncthreads();
    if (t < 128)
        smIZ[t] = 1.f / (zb[2 * t] + zb[2 * t + 1]);
    __syncthreads();

    // ---------------- Phase 2: normalize + PV ----------------
    const int g = lane >> 2, tig = lane & 3;
    float iz0 = smIZ[16 * wid + g];
    float iz1 = smIZ[16 * wid + 8 + g];

    float cacc[8][4];
#pragma unroll
    for (int nt = 0; nt < 8; nt++)
#pragma unroll
        for (int r = 0; r < 4; r++) cacc[nt][r] = 0.f;

    const int btrow = (lane & 15) * 144;

    for (int kt = 0; kt <= qt; kt++) {
        const int k0 = kt * 128;
        __syncthreads();                       // V smem (OKH/OKL) free
        float4 vbuf[8];
#pragma unroll
        for (int jj = 0; jj < 8; jj++)
            vbuf[jj] = *((const float4*)(Vg + (size_t)(k0 + lr + 16 * jj) * 64 + 4 * lc4));
#pragma unroll
        for (int jj = 0; jj < 8; jj++)
            split72(sm + OKH, sm + OKL, lr + 16 * jj, lc4, vbuf[jj]);
        __syncthreads();                       // V visible

        float* rp0 = attng + (size_t)(q0 + 16 * wid + g) * LSEQ + k0 + 2 * tig;
        float* rp1 = attng + (size_t)(q0 + 16 * wid + 8 + g) * LSEQ + k0 + 2 * tig;

#pragma unroll 1
        for (int ks = 0; ks < 8; ks++) {
            float2 p00 = *((const float2*)(rp0 + 16 * ks));
            float2 p10 = *((const float2*)(rp1 + 16 * ks));
            float2 p01 = *((const float2*)(rp0 + 16 * ks + 8));
            float2 p11 = *((const float2*)(rp1 + 16 * ks + 8));
            p00.x *= iz0; p00.y *= iz0; p01.x *= iz0; p01.y *= iz0;
            p10.x *= iz1; p10.y *= iz1; p11.x *= iz1; p11.y *= iz1;
            *((float2*)(rp0 + 16 * ks))     = p00;
            *((float2*)(rp1 + 16 * ks))     = p10;
            *((float2*)(rp0 + 16 * ks + 8)) = p01;
            *((float2*)(rp1 + 16 * ks + 8)) = p11;
            uint32_t PH[4], PL[4];
            PH[0] = pkbf(p00.x, p00.y);
            PH[1] = pkbf(p10.x, p10.y);
            PH[2] = pkbf(p01.x, p01.y);
            PH[3] = pkbf(p11.x, p11.y);
            {
                float hx, hy;
                hx = __bfloat162float(__float2bfloat16(p00.x));
                hy = __bfloat162float(__float2bfloat16(p00.y));
                PL[0] = pkbf(p00.x - hx, p00.y - hy);
                hx = __bfloat162float(__float2bfloat16(p10.x));
                hy = __bfloat162float(__float2bfloat16(p10.y));
                PL[1] = pkbf(p10.x - hx, p10.y - hy);
                hx = __bfloat162float(__float2bfloat16(p01.x));
                hy = __bfloat162float(__float2bfloat16(p01.y));
                PL[2] = pkbf(p01.x - hx, p01.y - hy);
                hx = __bfloat162float(__float2bfloat16(p11.x));
                hy = __bfloat162float(__float2bfloat16(p11.y));
                PL[3] = pkbf(p11.x - hx, p11.y - hy);
            }
#pragma unroll
            for (int nt = 0; nt < 8; nt++) {
                uint32_t BH[2], BL[2];
                uint32_t bo = (uint32_t)(16 * ks * 144) + btrow + nt * 16;
                ldmBT(BH, sb + OKH + bo);
                ldmBT(BL, sb + OKL + bo);
                mmabf(cacc[nt], PH, BH);
                mmabf(cacc[nt], PH, BL);
                mmabf(cacc[nt], PL, BH);
            }
        }
    }

    // zero-fill future columns
    const int kend = (qt + 1) * 128;
    const int nz = (LSEQ - kend) >> 2;
    if (nz > 0) {
        const float4 z4 = make_float4(0.f, 0.f, 0.f, 0.f);
        for (int i = t; i < 128 * nz; i += 256) {
            int r = i / nz, c = i - r * nz;
            *((float4*)(attng + (size_t)(q0 + r) * LSEQ + kend + 4 * c)) = z4;
        }
    }

    // ctx epilogue
#pragma unroll
    for (int nt = 0; nt < 8; nt++)
#pragma unroll
        for (int rh = 0; rh < 2; rh++) {
            int q = q0 + 16 * wid + 8 * rh + g;
            int d = 8 * nt + 2 * tig;
            *((float2*)(ctxg + (size_t)q * 64 + d)) =
                make_float2(cacc[nt][2 * rh], cacc[nt][2 * rh + 1]);
        }
}

extern "C" void kernel_launch(void* const* d_in, const int* in_sizes, int n_in,
                              void* d_out, int out_size) {
    const float* Q  = (const float*)d_in[0];
    const float* K  = (const float*)d_in[1];
    const float* V  = (const float*)d_in[2];
    const float* Er = (const float*)d_in[4];

    const long long CTXN = (long long)2 * 16 * 2048 * 64;
    const long long ATTN = (long long)2 * 16 * 2048 * 2048;
    float* out = (float*)d_out;
    float* ctx; float* attn;
    if ((long long)out_size >= CTXN + ATTN) { ctx = out; attn = out + CTXN; }
    else if ((long long)out_size == ATTN)   { ctx = nullptr; attn = out; }
    else                                    { ctx = out; attn = out; }

    cudaFuncSetAttribute(fused_attn, cudaFuncAttributeMaxDynamicSharedMemorySize, SMEM_TOT);
    fused_attn<<<dim3(16, 32), 256, SMEM_TOT>>>(Q, K, Er, V, ctx, attn);
}

// round 12
// speedup vs baseline: 1.1677x; 1.1677x over previous
#include <cuda_runtime.h>
#include <cuda_bf16.h>
#include <cstdint>

#define LSEQ 2048
typedef unsigned long long ull;

__device__ float g_IZ[32 * LSEQ];
__device__ float g_ctx_scratch[2 * 16 * 2048 * 64];

// ---- score kernel smem (operand pitch 72 bf16 = 144B rows) ----
#define OKH 0
#define OKL 18432
#define OEH 36864
#define OEL 55296
#define ORS 73728
#define RSPITCH 260
#define SMEM_TOT (73728 + 128 * RSPITCH * 4)   // 206848

__device__ __forceinline__ uint32_t smem_u32(const void* p) {
    uint32_t a;
    asm("{ .reg .u64 t; cvta.to.shared.u64 t, %1; cvt.u32.u64 %0, t; }" : "=r"(a) : "l"(p));
    return a;
}
__device__ __forceinline__ void ldmA(uint32_t* a, uint32_t addr) {
    asm volatile("ldmatrix.sync.aligned.m8n8.x4.shared.b16 {%0,%1,%2,%3}, [%4];"
        : "=r"(a[0]), "=r"(a[1]), "=r"(a[2]), "=r"(a[3]) : "r"(addr));
}
__device__ __forceinline__ void ldmB(uint32_t* b, uint32_t addr) {
    asm volatile("ldmatrix.sync.aligned.m8n8.x2.shared.b16 {%0,%1}, [%2];"
        : "=r"(b[0]), "=r"(b[1]) : "r"(addr));
}
__device__ __forceinline__ void ldmBT(uint32_t* b, uint32_t addr) {
    asm volatile("ldmatrix.sync.aligned.m8n8.x2.trans.shared.b16 {%0,%1}, [%2];"
        : "=r"(b[0]), "=r"(b[1]) : "r"(addr));
}
__device__ __forceinline__ void mmabf(float* d, const uint32_t* a, const uint32_t* b) {
    asm volatile("mma.sync.aligned.m16n8k16.row.col.f32.bf16.bf16.f32 "
        "{%0,%1,%2,%3}, {%4,%5,%6,%7}, {%8,%9}, {%0,%1,%2,%3};"
        : "+f"(d[0]), "+f"(d[1]), "+f"(d[2]), "+f"(d[3])
        : "r"(a[0]), "r"(a[1]), "r"(a[2]), "r"(a[3]), "r"(b[0]), "r"(b[1]));
}
__device__ __forceinline__ uint32_t pkbf(float a, float b) {
    __nv_bfloat162 h = __floats2bfloat162_rn(a, b);
    return *(uint32_t*)&h;
}
__device__ __forceinline__ void split72(char* hi, char* lo, int r, int c4, float4 v) {
    float hx = __bfloat162float(__float2bfloat16(v.x));
    float hy = __bfloat162float(__float2bfloat16(v.y));
    float hz = __bfloat162float(__float2bfloat16(v.z));
    float hw = __bfloat162float(__float2bfloat16(v.w));
    int off = r * 144 + c4 * 8;
    *(uint2*)(hi + off) = make_uint2(pkbf(v.x, v.y), pkbf(v.z, v.w));
    *(uint2*)(lo + off) = make_uint2(pkbf(v.x - hx, v.y - hy), pkbf(v.z - hz, v.w - hw));
}
__device__ __forceinline__ void split136(char* hi, char* lo, int r, int c4, float4 v) {
    float hx = __bfloat162float(__float2bfloat16(v.x));
    float hy = __bfloat162float(__float2bfloat16(v.y));
    float hz = __bfloat162float(__float2bfloat16(v.z));
    float hw = __bfloat162float(__float2bfloat16(v.w));
    int off = r * 272 + c4 * 8;
    *(uint2*)(hi + off) = make_uint2(pkbf(v.x, v.y), pkbf(v.z, v.w));
    *(uint2*)(lo + off) = make_uint2(pkbf(v.x - hx, v.y - hy), pkbf(v.z - hz, v.w - hw));
}

// ========== Kernel A: scores, incremental R ring + K/E prefetch (R10) ======
__global__ void __launch_bounds__(256, 1)
score_mma(const float* __restrict__ Q, const float* __restrict__ K,
          const float* __restrict__ Er, float* __restrict__ attn)
{
    extern __shared__ char sm[];
    const uint32_t sb = smem_u32(sm);
    float* Rs = (float*)(sm + ORS);

    const int qt = 15 - (int)blockIdx.x;
    const int bh = blockIdx.y;
    const int q0 = qt * 128;
    const int t = threadIdx.x;
    const int wid = t >> 5, lane = t & 31;
    const int wm = wid >> 1, wn = wid & 1;

    const float* Qg = Q + (size_t)bh * LSEQ * 64;
    const float* Kg = K + (size_t)bh * LSEQ * 64;
    float* attng = attn + (size_t)bh * LSEQ * LSEQ;

    for (int i = t; i < 2048; i += 256) {
        int r = i >> 4, c4 = i & 15;
        split72(sm + ORS, sm + ORS + 18432, r, c4,
                *((const float4*)(Qg + (size_t)(q0 + r) * 64 + 4 * c4)));
    }
    __syncthreads();

    const int arow = (lane & 7) + 8 * ((lane >> 3) & 1);
    const int acolB = 16 * (lane >> 4);
    uint32_t AH[2][4][4], AL[2][4][4];
#pragma unroll
    for (int mt = 0; mt < 2; mt++)
#pragma unroll
        for (int ks = 0; ks < 4; ks++) {
            uint32_t ro = (uint32_t)((32 * wm + 16 * mt + arow) * 144 + ks * 32 + acolB);
            ldmA(AH[mt][ks], sb + ORS + ro);
            ldmA(AL[mt][ks], sb + ORS + 18432 + ro);
        }

    const int browB = (lane & 7) * 144;
    const int bcolB = 16 * ((lane >> 3) & 1);
    float zacc[2][2] = {{0.f, 0.f}, {0.f, 0.f}};

    const int lr = t >> 4, lc4 = t & 15;

    float4 kb[8], eb[8];
    {
        const int k0 = qt * 128;
#pragma unroll
        for (int jj = 0; jj < 8; jj++)
            kb[jj] = *((const float4*)(Kg + (size_t)(k0 + lr + 16 * jj) * 64 + 4 * lc4));
#pragma unroll
        for (int jj = 0; jj < 8; jj++)
            eb[jj] = *((const float4*)(Er + (size_t)(2047 - (lr + 16 * jj)) * 64 + 4 * lc4));
    }

    for (int h = 0; h <= qt; h++) {
        const int k0 = (qt - h) * 128;
        __syncthreads();

#pragma unroll
        for (int jj = 0; jj < 8; jj++)
            split72(sm + OKH, sm + OKL, lr + 16 * jj, lc4, kb[jj]);
#pragma unroll
        for (int jj = 0; jj < 8; jj++)
            split72(sm + OEH, sm + OEL, lr + 16 * jj, lc4, eb[jj]);

        if (h < qt) {
            const int k0n = (qt - h - 1) * 128;
            const int ebn = 2047 - 128 * (h + 1);
#pragma unroll
            for (int jj = 0; jj < 8; jj++)
                kb[jj] = *((const float4*)(Kg + (size_t)(k0n + lr + 16 * jj) * 64 + 4 * lc4));
#pragma unroll
            for (int jj = 0; jj < 8; jj++)
                eb[jj] = *((const float4*)(Er + (size_t)(ebn - (lr + 16 * jj)) * 64 + 4 * lc4));
        }
        __syncthreads();

        const int slotW = 128 * ((h + 1) & 1);
#pragma unroll 1
        for (int nt = 0; nt < 8; nt++) {
            float racc[2][4] = {{0.f, 0.f, 0.f, 0.f}, {0.f, 0.f, 0.f, 0.f}};
            const uint32_t nb = (uint32_t)((64 * wn + 8 * nt) * 144) + browB + bcolB;
#pragma unroll
            for (int ks = 0; ks < 4; ks++) {
                uint32_t BH[2], BL[2];
                ldmB(BH, sb + OEH + nb + ks * 32);
                ldmB(BL, sb + OEL + nb + ks * 32);
#pragma unroll
                for (int mt = 0; mt < 2; mt++) {
                    mmabf(racc[mt], AH[mt][ks], BH);
                    mmabf(racc[mt], AH[mt][ks], BL);
                    mmabf(racc[mt], AL[mt][ks], BH);
                }
            }
            const int c = slotW + 64 * wn + 8 * nt + 2 * (lane & 3);
#pragma unroll
            for (int mt = 0; mt < 2; mt++) {
                int q = 32 * wm + 16 * mt + (lane >> 2);
                *((float2*)(Rs + q * RSPITCH + c)) = make_float2(racc[mt][0], racc[mt][1]);
                *((float2*)(Rs + (q + 8) * RSPITCH + c)) = make_float2(racc[mt][2], racc[mt][3]);
            }
        }
        __syncthreads();

        const int sA = 128 * ((h + 1) & 1);
        const int sB = 128 * (h & 1);
        const bool diag = (h == 0);
#pragma unroll 1
        for (int kh = 0; kh < 2; kh++) {
            float sacc[2][4][4];
#pragma unroll
            for (int mt = 0; mt < 2; mt++)
#pragma unroll
                for (int nt = 0; nt < 4; nt++)
#pragma unroll
                    for (int r = 0; r < 4; r++) sacc[mt][nt][r] = 0.f;
#pragma unroll
            for (int nt = 0; nt < 4; nt++) {
                const uint32_t nb = (uint32_t)((64 * kh + 32 * wn + 8 * nt) * 144) + browB + bcolB;
#pragma unroll
                for (int ks = 0; ks < 4; ks++) {
                    uint32_t BH[2], BL[2];
                    ldmB(BH, sb + OKH + nb + ks * 32);
                    ldmB(BL, sb + OKL + nb + ks * 32);
#pragma unroll
                    for (int mt = 0; mt < 2; mt++) {
                        mmabf(sacc[mt][nt], AH[mt][ks], BH);
                        mmabf(sacc[mt][nt], AH[mt][ks], BL);
                        mmabf(sacc[mt][nt], AL[mt][ks], BH);
                    }
                }
            }
#pragma unroll
            for (int mt = 0; mt < 2; mt++) {
#pragma unroll
                for (int nt = 0; nt < 4; nt++) {
                    const int klocal = 64 * kh + 32 * wn + 8 * nt + 2 * (lane & 3);
                    const int kg = k0 + klocal;
#pragma unroll
                    for (int rh = 0; rh < 2; rh++) {
                        const int r = 32 * wm + 16 * mt + 8 * rh + (lane >> 2);
                        const int qg = q0 + r;
                        const int d0 = r - klocal;
                        const int d1 = d0 - 1;
                        float r0 = Rs[r * RSPITCH + ((d0 & 127) + (d0 >= 0 ? sA : sB))];
                        float r1 = Rs[r * RSPITCH + ((d1 & 127) + (d1 >= 0 ? sA : sB))];
                        float s0 = (sacc[mt][nt][2 * rh] + r0) * 0.125f;
                        float s1 = (sacc[mt][nt][2 * rh + 1] + r1) * 0.125f;
                        float p0 = __expf(s0), p1 = __expf(s1);
                        if (diag) {
                            if (kg > qg) p0 = 0.f;
                            if (kg + 1 > qg) p1 = 0.f;
                        }
                        zacc[mt][rh] += p0 + p1;
                        *((float2*)(attng + (size_t)qg * LSEQ + kg)) = make_float2(p0, p1);
                    }
                }
            }
        }
    }

#pragma unroll
    for (int mt = 0; mt < 2; mt++)
#pragma unroll
        for (int rh = 0; rh < 2; rh++) {
            float v = zacc[mt][rh];
            v += __shfl_xor_sync(0xffffffffu, v, 1);
            v += __shfl_xor_sync(0xffffffffu, v, 2);
            zacc[mt][rh] = v;
        }
    __syncthreads();
    float* zb = Rs;
    if ((lane & 3) == 0) {
#pragma unroll
        for (int mt = 0; mt < 2; mt++)
#pragma unroll
            for (int rh = 0; rh < 2; rh++) {
                int row = 32 * wm + 16 * mt + 8 * rh + (lane >> 2);
                zb[row * 2 + wn] = zacc[mt][rh];
            }
    }
    __syncthreads();
    if (t < 128)
        g_IZ[bh * LSEQ + q0 + t] = 1.f / (zb[2 * t] + zb[2 * t + 1]);
}

// ========== Kernel B: TC PV, 64-row q tiles, 3 CTAs/SM ==========
// smem: P hi [64][136bf16] | P lo | V hi [128][72bf16] | V lo | iz[64]
#define PPH 0
#define PPL 17408
#define PVH 34816
#define PVL 53248
#define PIZ 71680
#define SMEM_PV 71936

__global__ void __launch_bounds__(256, 3)
pv_tc(const float* __restrict__ V, float* __restrict__ ctx, float* __restrict__ attn)
{
    extern __shared__ char sm[];
    const uint32_t sb = smem_u32(sm);
    float* smIZ = (float*)(sm + PIZ);
    if (ctx == nullptr) ctx = g_ctx_scratch;

    const int qt = 31 - (int)blockIdx.x;
    const int bh = blockIdx.y;
    const int q0 = qt * 64;
    const int t = threadIdx.x;
    const int wid = t >> 5, lane = t & 31;
    const int wm = wid >> 1, wn = wid & 1;

    const float* Vg = V + (size_t)bh * LSEQ * 64;
    float* attng = attn + (size_t)bh * LSEQ * LSEQ;
    float* ctxg = ctx + (size_t)bh * LSEQ * 64;

    if (t < 64) smIZ[t] = g_IZ[bh * LSEQ + q0 + t];
    __syncthreads();

    float cacc[4][4];
#pragma unroll
    for (int nt = 0; nt < 4; nt++)
#pragma unroll
        for (int r = 0; r < 4; r++) cacc[nt][r] = 0.f;

    const int arow = (lane & 7) + 8 * ((lane >> 3) & 1);
    const int acolB = 16 * (lane >> 4);
    const int btrow = (lane & 15) * 144;
    const int bncol = (32 * wn) * 2;

    const int vr = t >> 4, vc4 = t & 15;
    const int pr = t >> 5, pc4 = t & 31;

    const int ktmax = qt >> 1;
    for (int kt = 0; kt <= ktmax; kt++) {
        const int k0 = kt * 128;
        __syncthreads();

        // batched V tile load + split (128 rows)
        float4 vbuf[8];
#pragma unroll
        for (int jj = 0; jj < 8; jj++)
            vbuf[jj] = *((const float4*)(Vg + (size_t)(k0 + vr + 16 * jj) * 64 + 4 * vc4));
#pragma unroll
        for (int jj = 0; jj < 8; jj++)
            split72(sm + PVH, sm + PVL, vr + 16 * jj, vc4, vbuf[jj]);

        // batched P tile load (64 rows x 128 cols), normalize, writeback, split
        float4 pbuf[8];
#pragma unroll
        for (int jj = 0; jj < 8; jj++)
            pbuf[jj] = *((const float4*)(attng +
                (size_t)(q0 + pr + 8 * jj) * LSEQ + k0 + 4 * pc4));
#pragma unroll
        for (int jj = 0; jj < 8; jj++) {
            int r = pr + 8 * jj;
            float iz = smIZ[r];
            float4 pv = pbuf[jj];
            pv.x *= iz; pv.y *= iz; pv.z *= iz; pv.w *= iz;
            *((float4*)(attng + (size_t)(q0 + r) * LSEQ + k0 + 4 * pc4)) = pv;
            split136(sm + PPH, sm + PPL, r, pc4, pv);
        }
        __syncthreads();

#pragma unroll 2
        for (int ks = 0; ks < 8; ks++) {
            uint32_t PH[4], PL[4];
            {
                uint32_t ro = (uint32_t)((16 * wm + arow) * 272 + ks * 32 + acolB);
                ldmA(PH, sb + PPH + ro);
                ldmA(PL, sb + PPL + ro);
            }
#pragma unroll
            for (int nt = 0; nt < 4; nt++) {
                uint32_t BH[2], BL[2];
                uint32_t bo = (uint32_t)(16 * ks * 144) + btrow + bncol + nt * 16;
                ldmBT(BH, sb + PVH + bo);
                ldmBT(BL, sb + PVL + bo);
                mmabf(cacc[nt], PH, BH);
                mmabf(cacc[nt], PH, BL);
                mmabf(cacc[nt], PL, BH);
            }
        }
    }

    // zero-fill future columns of this 64-row slab
    const int kend = (ktmax + 1) * 128;
    const int nz = (LSEQ - kend) >> 2;
    if (nz > 0) {
        const float4 z4 = make_float4(0.f, 0.f, 0.f, 0.f);
        for (int i = t; i < 64 * nz; i += 256) {
            int r = i / nz, c = i - r * nz;
            *((float4*)(attng + (size_t)(q0 + r) * LSEQ + kend + 4 * c)) = z4;
        }
    }

    // ctx epilogue (16 rows x 32 cols per warp)
#pragma unroll
    for (int nt = 0; nt < 4; nt++)
#pragma unroll
        for (int rh = 0; rh < 2; rh++) {
            int q = q0 + 16 * wm + 8 * rh + (lane >> 2);
            int d = 32 * wn + 8 * nt + 2 * (lane & 3);
            *((float2*)(ctxg + (size_t)q * 64 + d)) =
                make_float2(cacc[nt][2 * rh], cacc[nt][2 * rh + 1]);
        }
}

extern "C" void kernel_launch(void* const* d_in, const int* in_sizes, int n_in,
                              void* d_out, int out_size) {
    const float* Q  = (const float*)d_in[0];
    const float* K  = (const float*)d_in[1];
    const float* V  = (const float*)d_in[2];
    const float* Er = (const float*)d_in[4];

    const long long CTXN = (long long)2 * 16 * 2048 * 64;
    const long long ATTN = (long long)2 * 16 * 2048 * 2048;
    float* out = (float*)d_out;
    float* ctx; float* attn;
    if ((long long)out_size >= CTXN + ATTN) { ctx = out; attn = out + CTXN; }
    else if ((long long)out_size == ATTN)   { ctx = nullptr; attn = out; }
    else                                    { ctx = out; attn = out; }

    cudaFuncSetAttribute(score_mma, cudaFuncAttributeMaxDynamicSharedMemorySize, SMEM_TOT);
    score_mma<<<dim3(16, 32), 256, SMEM_TOT>>>(Q, K, Er, attn);

    cudaFuncSetAttribute(pv_tc, cudaFuncAttributeMaxDynamicSharedMemorySize, SMEM_PV);
    pv_tc<<<dim3(32, 32), 256, SMEM_PV>>>(V, ctx, attn);
}

// round 14
// speedup vs baseline: 1.2438x; 1.0652x over previous
#include <cuda_runtime.h>
#include <cuda_bf16.h>
#include <cstdint>

#define LSEQ 2048
typedef unsigned long long ull;

__device__ float g_IZ[32 * LSEQ];
__device__ float g_ctx_scratch[2 * 16 * 2048 * 64];

__device__ __forceinline__ uint32_t smem_u32(const void* p) {
    uint32_t a;
    asm("{ .reg .u64 t; cvta.to.shared.u64 t, %1; cvt.u32.u64 %0, t; }" : "=r"(a) : "l"(p));
    return a;
}
__device__ __forceinline__ void ldmA(uint32_t* a, uint32_t addr) {
    asm volatile("ldmatrix.sync.aligned.m8n8.x4.shared.b16 {%0,%1,%2,%3}, [%4];"
        : "=r"(a[0]), "=r"(a[1]), "=r"(a[2]), "=r"(a[3]) : "r"(addr));
}
__device__ __forceinline__ void ldmB(uint32_t* b, uint32_t addr) {
    asm volatile("ldmatrix.sync.aligned.m8n8.x2.shared.b16 {%0,%1}, [%2];"
        : "=r"(b[0]), "=r"(b[1]) : "r"(addr));
}
__device__ __forceinline__ void ldmBT(uint32_t* b, uint32_t addr) {
    asm volatile("ldmatrix.sync.aligned.m8n8.x2.trans.shared.b16 {%0,%1}, [%2];"
        : "=r"(b[0]), "=r"(b[1]) : "r"(addr));
}
__device__ __forceinline__ void mmabf(float* d, const uint32_t* a, const uint32_t* b) {
    asm volatile("mma.sync.aligned.m16n8k16.row.col.f32.bf16.bf16.f32 "
        "{%0,%1,%2,%3}, {%4,%5,%6,%7}, {%8,%9}, {%0,%1,%2,%3};"
        : "+f"(d[0]), "+f"(d[1]), "+f"(d[2]), "+f"(d[3])
        : "r"(a[0]), "r"(a[1]), "r"(a[2]), "r"(a[3]), "r"(b[0]), "r"(b[1]));
}
__device__ __forceinline__ uint32_t pkbf(float a, float b) {
    __nv_bfloat162 h = __floats2bfloat162_rn(a, b);
    return *(uint32_t*)&h;
}
__device__ __forceinline__ void split72(char* hi, char* lo, int r, int c4, float4 v) {
    float hx = __bfloat162float(__float2bfloat16(v.x));
    float hy = __bfloat162float(__float2bfloat16(v.y));
    float hz = __bfloat162float(__float2bfloat16(v.z));
    float hw = __bfloat162float(__float2bfloat16(v.w));
    int off = r * 144 + c4 * 8;
    *(uint2*)(hi + off) = make_uint2(pkbf(v.x, v.y), pkbf(v.z, v.w));
    *(uint2*)(lo + off) = make_uint2(pkbf(v.x - hx, v.y - hy), pkbf(v.z - hz, v.w - hw));
}
__device__ __forceinline__ void split136(char* hi, char* lo, int r, int c4, float4 v) {
    float hx = __bfloat162float(__float2bfloat16(v.x));
    float hy = __bfloat162float(__float2bfloat16(v.y));
    float hz = __bfloat162float(__float2bfloat16(v.z));
    float hw = __bfloat162float(__float2bfloat16(v.w));
    int off = r * 272 + c4 * 8;
    *(uint2*)(hi + off) = make_uint2(pkbf(v.x, v.y), pkbf(v.z, v.w));
    *(uint2*)(lo + off) = make_uint2(pkbf(v.x - hx, v.y - hy), pkbf(v.z - hz, v.w - hw));
}

// ========== Kernel A: 64x64-tiled scores, incremental R ring, 2 CTAs/SM ====
#define SKH 0
#define SKL 9216
#define SEH 18432
#define SEL 27648
#define SRS 36864
#define SRSP 132
#define SMEM_SC (36864 + 64 * SRSP * 4)   // 70656

__global__ void __launch_bounds__(256, 2)
score_mma(const float* __restrict__ Q, const float* __restrict__ K,
          const float* __restrict__ Er, float* __restrict__ attn)
{
    extern __shared__ char sm[];
    const uint32_t sb = smem_u32(sm);
    float* Rs = (float*)(sm + SRS);

    const int qt = 31 - (int)blockIdx.x;
    const int bh = blockIdx.y;
    const int q0 = qt * 64;
    const int t = threadIdx.x;
    const int wid = t >> 5, lane = t & 31;
    const int wm = wid >> 1;
    const int wn = wid & 1;

    const float* Qg = Q + (size_t)bh * LSEQ * 64;
    const float* Kg = K + (size_t)bh * LSEQ * 64;
    float* attng = attn + (size_t)bh * LSEQ * LSEQ;

    for (int i = t; i < 1024; i += 256) {
        int r = i >> 4, c4 = i & 15;
        split72(sm + SRS, sm + SRS + 9216, r, c4,
                *((const float4*)(Qg + (size_t)(q0 + r) * 64 + 4 * c4)));
    }
    __syncthreads();

    const int arow = (lane & 7) + 8 * ((lane >> 3) & 1);
    const int acolB = 16 * (lane >> 4);
    uint32_t AH[4][4], AL[4][4];
#pragma unroll
    for (int ks = 0; ks < 4; ks++) {
        uint32_t ro = (uint32_t)((16 * wm + arow) * 144 + ks * 32 + acolB);
        ldmA(AH[ks], sb + SRS + ro);
        ldmA(AL[ks], sb + SRS + 9216 + ro);
    }

    const int browB = (lane & 7) * 144;
    const int bcolB = 16 * ((lane >> 3) & 1);
    float zacc[2] = {0.f, 0.f};

    const int lr = t >> 4, lc4 = t & 15;

    float4 kb[4], eb[4];
    {
        const int k0 = qt * 64;
#pragma unroll
        for (int jj = 0; jj < 4; jj++)
            kb[jj] = *((const float4*)(Kg + (size_t)(k0 + lr + 16 * jj) * 64 + 4 * lc4));
#pragma unroll
        for (int jj = 0; jj < 4; jj++)
            eb[jj] = *((const float4*)(Er + (size_t)(2047 - (lr + 16 * jj)) * 64 + 4 * lc4));
    }

    for (int h = 0; h <= qt; h++) {
        const int k0 = (qt - h) * 64;
        __syncthreads();

#pragma unroll
        for (int jj = 0; jj < 4; jj++)
            split72(sm + SKH, sm + SKL, lr + 16 * jj, lc4, kb[jj]);
#pragma unroll
        for (int jj = 0; jj < 4; jj++)
            split72(sm + SEH, sm + SEL, lr + 16 * jj, lc4, eb[jj]);

        if (h < qt) {
            const int k0n = (qt - h - 1) * 64;
            const int ebn = 2047 - 64 * (h + 1);
#pragma unroll
            for (int jj = 0; jj < 4; jj++)
                kb[jj] = *((const float4*)(Kg + (size_t)(k0n + lr + 16 * jj) * 64 + 4 * lc4));
#pragma unroll
            for (int jj = 0; jj < 4; jj++)
                eb[jj] = *((const float4*)(Er + (size_t)(ebn - (lr + 16 * jj)) * 64 + 4 * lc4));
        }
        __syncthreads();

        const int slotW = 64 * (h & 1);
#pragma unroll
        for (int nt = 0; nt < 4; nt++) {
            float racc[4] = {0.f, 0.f, 0.f, 0.f};
            const uint32_t nb = (uint32_t)((32 * wn + 8 * nt) * 144) + browB + bcolB;
#pragma unroll
            for (int ks = 0; ks < 4; ks++) {
                uint32_t BH[2], BL[2];
                ldmB(BH, sb + SEH + nb + ks * 32);
                ldmB(BL, sb + SEL + nb + ks * 32);
                mmabf(racc, AH[ks], BH);
                mmabf(racc, AH[ks], BL);
                mmabf(racc, AL[ks], BH);
            }
            const int c = slotW + 32 * wn + 8 * nt + 2 * (lane & 3);
            const int q = 16 * wm + (lane >> 2);
            *((float2*)(Rs + q * SRSP + c)) = make_float2(racc[0], racc[1]);
            *((float2*)(Rs + (q + 8) * SRSP + c)) = make_float2(racc[2], racc[3]);
        }
        __syncthreads();

        float sacc[4][4];
#pragma unroll
        for (int nt = 0; nt < 4; nt++)
#pragma unroll
            for (int r = 0; r < 4; r++) sacc[nt][r] = 0.f;
#pragma unroll
        for (int nt = 0; nt < 4; nt++) {
            const uint32_t nb = (uint32_t)((32 * wn + 8 * nt) * 144) + browB + bcolB;
#pragma unroll
            for (int ks = 0; ks < 4; ks++) {
                uint32_t BH[2], BL[2];
                ldmB(BH, sb + SKH + nb + ks * 32);
                ldmB(BL, sb + SKL + nb + ks * 32);
                mmabf(sacc[nt], AH[ks], BH);
                mmabf(sacc[nt], AH[ks], BL);
                mmabf(sacc[nt], AL[ks], BH);
            }
        }
        const int s0 = 64 * (h & 1);
        const int s1 = 64 * ((h + 1) & 1);
        const bool diag = (h == 0);
#pragma unroll
        for (int nt = 0; nt < 4; nt++) {
            const int klocal = 32 * wn + 8 * nt + 2 * (lane & 3);
            const int kg = k0 + klocal;
#pragma unroll
            for (int rh = 0; rh < 2; rh++) {
                const int r = 16 * wm + 8 * rh + (lane >> 2);
                const int qg = q0 + r;
                const int d0 = r - klocal;
                const int d1 = d0 - 1;
                float r0 = Rs[r * SRSP + ((d0 & 63) + (d0 >= 0 ? s0 : s1))];
                float r1 = Rs[r * SRSP + ((d1 & 63) + (d1 >= 0 ? s0 : s1))];
                float sv0 = (sacc[nt][2 * rh] + r0) * 0.125f;
                float sv1 = (sacc[nt][2 * rh + 1] + r1) * 0.125f;
                float p0 = __expf(sv0), p1 = __expf(sv1);
                if (diag) {
                    if (kg > qg) p0 = 0.f;
                    if (kg + 1 > qg) p1 = 0.f;
                }
                zacc[rh] += p0 + p1;
                *((float2*)(attng + (size_t)qg * LSEQ + kg)) = make_float2(p0, p1);
            }
        }
    }

#pragma unroll
    for (int rh = 0; rh < 2; rh++) {
        float v = zacc[rh];
        v += __shfl_xor_sync(0xffffffffu, v, 1);
        v += __shfl_xor_sync(0xffffffffu, v, 2);
        zacc[rh] = v;
    }
    __syncthreads();
    float* zb = Rs;
    if ((lane & 3) == 0) {
#pragma unroll
        for (int rh = 0; rh < 2; rh++) {
            int row = 16 * wm + 8 * rh + (lane >> 2);
            zb[row * 2 + wn] = zacc[rh];
        }
    }
    __syncthreads();
    if (t < 64)
        g_IZ[bh * LSEQ + q0 + t] = 1.f / (zb[2 * t] + zb[2 * t + 1]);
}

// ========== Kernel B: TC PV with uncovered-half-tile zeroing ==========
#define PPH 0
#define PPL 17408
#define PVH 34816
#define PVL 53248
#define PIZ 71680
#define SMEM_PV 71936

__global__ void __launch_bounds__(256, 3)
pv_tc(const float* __restrict__ V, float* __restrict__ ctx, float* __restrict__ attn)
{
    extern __shared__ char sm[];
    const uint32_t sb = smem_u32(sm);
    float* smIZ = (float*)(sm + PIZ);
    if (ctx == nullptr) ctx = g_ctx_scratch;

    const int qt = 31 - (int)blockIdx.x;
    const int bh = blockIdx.y;
    const int q0 = qt * 64;
    const int t = threadIdx.x;
    const int wid = t >> 5, lane = t & 31;
    const int wm = wid >> 1, wn = wid & 1;

    const float* Vg = V + (size_t)bh * LSEQ * 64;
    float* attng = attn + (size_t)bh * LSEQ * LSEQ;
    float* ctxg = ctx + (size_t)bh * LSEQ * 64;

    if (t < 64) smIZ[t] = g_IZ[bh * LSEQ + q0 + t];
    __syncthreads();

    float cacc[4][4];
#pragma unroll
    for (int nt = 0; nt < 4; nt++)
#pragma unroll
        for (int r = 0; r < 4; r++) cacc[nt][r] = 0.f;

    const int arow = (lane & 7) + 8 * ((lane >> 3) & 1);
    const int acolB = 16 * (lane >> 4);
    const int btrow = (lane & 15) * 144;
    const int bncol = (32 * wn) * 2;

    const int vr = t >> 4, vc4 = t & 15;
    const int pr = t >> 5, pc4 = t & 31;

    const int kcov = (qt + 1) * 64;          // score wrote cols [0, kcov)
    const int ktmax = qt >> 1;
    for (int kt = 0; kt <= ktmax; kt++) {
        const int k0 = kt * 128;
        // columns k0+4*pc4..+3 of this thread; beyond score coverage -> exact 0
        const bool oob = (k0 + 4 * pc4) >= kcov;
        __syncthreads();

        float4 vbuf[8];
#pragma unroll
        for (int jj = 0; jj < 8; jj++)
            vbuf[jj] = *((const float4*)(Vg + (size_t)(k0 + vr + 16 * jj) * 64 + 4 * vc4));
#pragma unroll
        for (int jj = 0; jj < 8; jj++)
            split72(sm + PVH, sm + PVL, vr + 16 * jj, vc4, vbuf[jj]);

        float4 pbuf[8];
#pragma unroll
        for (int jj = 0; jj < 8; jj++)
            pbuf[jj] = *((const float4*)(attng +
                (size_t)(q0 + pr + 8 * jj) * LSEQ + k0 + 4 * pc4));
#pragma unroll
        for (int jj = 0; jj < 8; jj++) {
            int r = pr + 8 * jj;
            float iz = smIZ[r];
            float4 pv = pbuf[jj];
            pv.x *= iz; pv.y *= iz; pv.z *= iz; pv.w *= iz;
            if (oob) pv = make_float4(0.f, 0.f, 0.f, 0.f);
            *((float4*)(attng + (size_t)(q0 + r) * LSEQ + k0 + 4 * pc4)) = pv;
            split136(sm + PPH, sm + PPL, r, pc4, pv);
        }
        __syncthreads();

#pragma unroll 2
        for (int ks = 0; ks < 8; ks++) {
            uint32_t PH[4], PL[4];
            {
                uint32_t ro = (uint32_t)((16 * wm + arow) * 272 + ks * 32 + acolB);
                ldmA(PH, sb + PPH + ro);
                ldmA(PL, sb + PPL + ro);
            }
#pragma unroll
            for (int nt = 0; nt < 4; nt++) {
                uint32_t BH[2], BL[2];
                uint32_t bo = (uint32_t)(16 * ks * 144) + btrow + bncol + nt * 16;
                ldmBT(BH, sb + PVH + bo);
                ldmBT(BL, sb + PVL + bo);
                mmabf(cacc[nt], PH, BH);
                mmabf(cacc[nt], PH, BL);
                mmabf(cacc[nt], PL, BH);
            }
        }
    }

    const int kend = (ktmax + 1) * 128;
    const int nz = (LSEQ - kend) >> 2;
    if (nz > 0) {
        const float4 z4 = make_float4(0.f, 0.f, 0.f, 0.f);
        for (int i = t; i < 64 * nz; i += 256) {
            int r = i / nz, c = i - r * nz;
            *((float4*)(attng + (size_t)(q0 + r) * LSEQ + kend + 4 * c)) = z4;
        }
    }

#pragma unroll
    for (int nt = 0; nt < 4; nt++)
#pragma unroll
        for (int rh = 0; rh < 2; rh++) {
            int q = q0 + 16 * wm + 8 * rh + (lane >> 2);
            int d = 32 * wn + 8 * nt + 2 * (lane & 3);
            *((float2*)(ctxg + (size_t)q * 64 + d)) =
                make_float2(cacc[nt][2 * rh], cacc[nt][2 * rh + 1]);
        }
}

extern "C" void kernel_launch(void* const* d_in, const int* in_sizes, int n_in,
                              void* d_out, int out_size) {
    const float* Q  = (const float*)d_in[0];
    const float* K  = (const float*)d_in[1];
    const float* V  = (const float*)d_in[2];
    const float* Er = (const float*)d_in[4];

    const long long CTXN = (long long)2 * 16 * 2048 * 64;
    const long long ATTN = (long long)2 * 16 * 2048 * 2048;
    float* out = (float*)d_out;
    float* ctx; float* attn;
    if ((long long)out_size >= CTXN + ATTN) { ctx = out; attn = out + CTXN; }
    else if ((long long)out_size == ATTN)   { ctx = nullptr; attn = out; }
    else                                    { ctx = out; attn = out; }

    cudaFuncSetAttribute(score_mma, cudaFuncAttributeMaxDynamicSharedMemorySize, SMEM_SC);
    score_mma<<<dim3(32, 32), 256, SMEM_SC>>>(Q, K, Er, attn);

    cudaFuncSetAttribute(pv_tc, cudaFuncAttributeMaxDynamicSharedMemorySize, SMEM_PV);
    pv_tc<<<dim3(32, 32), 256, SMEM_PV>>>(V, ctx, attn);
}

// round 15
// speedup vs baseline: 1.3227x; 1.0634x over previous
#include <cuda_runtime.h>
#include <cuda_bf16.h>
#include <cstdint>

#define LSEQ 2048
typedef unsigned long long ull;

__device__ float g_ctx_scratch[2 * 16 * 2048 * 64];

__device__ __forceinline__ uint32_t smem_u32(const void* p) {
    uint32_t a;
    asm("{ .reg .u64 t; cvta.to.shared.u64 t, %1; cvt.u32.u64 %0, t; }" : "=r"(a) : "l"(p));
    return a;
}
__device__ __forceinline__ void ldmA(uint32_t* a, uint32_t addr) {
    asm volatile("ldmatrix.sync.aligned.m8n8.x4.shared.b16 {%0,%1,%2,%3}, [%4];"
        : "=r"(a[0]), "=r"(a[1]), "=r"(a[2]), "=r"(a[3]) : "r"(addr));
}
__device__ __forceinline__ void ldmB(uint32_t* b, uint32_t addr) {
    asm volatile("ldmatrix.sync.aligned.m8n8.x2.shared.b16 {%0,%1}, [%2];"
        : "=r"(b[0]), "=r"(b[1]) : "r"(addr));
}
__device__ __forceinline__ void ldmBT(uint32_t* b, uint32_t addr) {
    asm volatile("ldmatrix.sync.aligned.m8n8.x2.trans.shared.b16 {%0,%1}, [%2];"
        : "=r"(b[0]), "=r"(b[1]) : "r"(addr));
}
__device__ __forceinline__ void mmabf(float* d, const uint32_t* a, const uint32_t* b) {
    asm volatile("mma.sync.aligned.m16n8k16.row.col.f32.bf16.bf16.f32 "
        "{%0,%1,%2,%3}, {%4,%5,%6,%7}, {%8,%9}, {%0,%1,%2,%3};"
        : "+f"(d[0]), "+f"(d[1]), "+f"(d[2]), "+f"(d[3])
        : "r"(a[0]), "r"(a[1]), "r"(a[2]), "r"(a[3]), "r"(b[0]), "r"(b[1]));
}
__device__ __forceinline__ uint32_t pkbf(float a, float b) {
    __nv_bfloat162 h = __floats2bfloat162_rn(a, b);
    return *(uint32_t*)&h;
}
__device__ __forceinline__ void split72(char* hi, char* lo, int r, int c4, float4 v) {
    float hx = __bfloat162float(__float2bfloat16(v.x));
    float hy = __bfloat162float(__float2bfloat16(v.y));
    float hz = __bfloat162float(__float2bfloat16(v.z));
    float hw = __bfloat162float(__float2bfloat16(v.w));
    int off = r * 144 + c4 * 8;
    *(uint2*)(hi + off) = make_uint2(pkbf(v.x, v.y), pkbf(v.z, v.w));
    *(uint2*)(lo + off) = make_uint2(pkbf(v.x - hx, v.y - hy), pkbf(v.z - hz, v.w - hw));
}
__device__ __forceinline__ void split136(char* hi, char* lo, int r, int c4, float4 v) {
    float hx = __bfloat162float(__float2bfloat16(v.x));
    float hy = __bfloat162float(__float2bfloat16(v.y));
    float hz = __bfloat162float(__float2bfloat16(v.z));
    float hw = __bfloat162float(__float2bfloat16(v.w));
    int off = r * 272 + c4 * 8;
    *(uint2*)(hi + off) = make_uint2(pkbf(v.x, v.y), pkbf(v.z, v.w));
    *(uint2*)(lo + off) = make_uint2(pkbf(v.x - hx, v.y - hy), pkbf(v.z - hz, v.w - hw));
}

// ---- time-shared smem layout ----
// score phase: SKH 0 | SKL 9216 | SEH 18432 | SEL 27648 | ring SRS 36864 (64x132 f32)
// pv phase:    PPH 0 | PPL 17408 | PVH 34816 | PVL 53248
// both:        IZ at 71680 (written at phase boundary, read in pv)
#define SKH 0
#define SKL 9216
#define SEH 18432
#define SEL 27648
#define SRS 36864
#define SRSP 132
#define PPH 0
#define PPL 17408
#define PVH 34816
#define PVL 53248
#define OIZ 71680
#define SMEM_F 71936

__global__ void __launch_bounds__(256, 2)
fused_attn(const float* __restrict__ Q, const float* __restrict__ K,
           const float* __restrict__ Er, const float* __restrict__ V,
           float* __restrict__ ctx, float* __restrict__ attn)
{
    extern __shared__ char sm[];
    const uint32_t sb = smem_u32(sm);
    float* Rs = (float*)(sm + SRS);
    float* smIZ = (float*)(sm + OIZ);

    const int qt = 31 - (int)blockIdx.x;
    const int bh = blockIdx.y;
    const int q0 = qt * 64;
    const int t = threadIdx.x;
    const int wid = t >> 5, lane = t & 31;
    const int wm = wid >> 1;
    const int wn = wid & 1;

    if (ctx == nullptr) ctx = g_ctx_scratch;
    const float* Qg = Q + (size_t)bh * LSEQ * 64;
    const float* Kg = K + (size_t)bh * LSEQ * 64;
    const float* Vg = V + (size_t)bh * LSEQ * 64;
    float* attng = attn + (size_t)bh * LSEQ * LSEQ;
    float* ctxg = ctx + (size_t)bh * LSEQ * 64;

    const int lr = t >> 4, lc4 = t & 15;

    // ================= Phase 1: scores (R14 winner) =================
    {
        for (int i = t; i < 1024; i += 256) {
            int r = i >> 4, c4 = i & 15;
            split72(sm + SRS, sm + SRS + 9216, r, c4,
                    *((const float4*)(Qg + (size_t)(q0 + r) * 64 + 4 * c4)));
        }
        __syncthreads();

        const int arow = (lane & 7) + 8 * ((lane >> 3) & 1);
        const int acolB = 16 * (lane >> 4);
        uint32_t AH[4][4], AL[4][4];
#pragma unroll
        for (int ks = 0; ks < 4; ks++) {
            uint32_t ro = (uint32_t)((16 * wm + arow) * 144 + ks * 32 + acolB);
            ldmA(AH[ks], sb + SRS + ro);
            ldmA(AL[ks], sb + SRS + 9216 + ro);
        }

        const int browB = (lane & 7) * 144;
        const int bcolB = 16 * ((lane >> 3) & 1);
        float zacc[2] = {0.f, 0.f};

        float4 kb[4], eb[4];
        {
            const int k0 = qt * 64;
#pragma unroll
            for (int jj = 0; jj < 4; jj++)
                kb[jj] = *((const float4*)(Kg + (size_t)(k0 + lr + 16 * jj) * 64 + 4 * lc4));
#pragma unroll
            for (int jj = 0; jj < 4; jj++)
                eb[jj] = *((const float4*)(Er + (size_t)(2047 - (lr + 16 * jj)) * 64 + 4 * lc4));
        }

        for (int h = 0; h <= qt; h++) {
            const int k0 = (qt - h) * 64;
            __syncthreads();

#pragma unroll
            for (int jj = 0; jj < 4; jj++)
                split72(sm + SKH, sm + SKL, lr + 16 * jj, lc4, kb[jj]);
#pragma unroll
            for (int jj = 0; jj < 4; jj++)
                split72(sm + SEH, sm + SEL, lr + 16 * jj, lc4, eb[jj]);

            if (h < qt) {
                const int k0n = (qt - h - 1) * 64;
                const int ebn = 2047 - 64 * (h + 1);
#pragma unroll
                for (int jj = 0; jj < 4; jj++)
                    kb[jj] = *((const float4*)(Kg + (size_t)(k0n + lr + 16 * jj) * 64 + 4 * lc4));
#pragma unroll
                for (int jj = 0; jj < 4; jj++)
                    eb[jj] = *((const float4*)(Er + (size_t)(ebn - (lr + 16 * jj)) * 64 + 4 * lc4));
            }
            __syncthreads();

            const int slotW = 64 * (h & 1);
#pragma unroll
            for (int nt = 0; nt < 4; nt++) {
                float racc[4] = {0.f, 0.f, 0.f, 0.f};
                const uint32_t nb = (uint32_t)((32 * wn + 8 * nt) * 144) + browB + bcolB;
#pragma unroll
                for (int ks = 0; ks < 4; ks++) {
                    uint32_t BH[2], BL[2];
                    ldmB(BH, sb + SEH + nb + ks * 32);
                    ldmB(BL, sb + SEL + nb + ks * 32);
                    mmabf(racc, AH[ks], BH);
                    mmabf(racc, AH[ks], BL);
                    mmabf(racc, AL[ks], BH);
                }
                const int c = slotW + 32 * wn + 8 * nt + 2 * (lane & 3);
                const int q = 16 * wm + (lane >> 2);
                *((float2*)(Rs + q * SRSP + c)) = make_float2(racc[0], racc[1]);
                *((float2*)(Rs + (q + 8) * SRSP + c)) = make_float2(racc[2], racc[3]);
            }
            __syncthreads();

            float sacc[4][4];
#pragma unroll
            for (int nt = 0; nt < 4; nt++)
#pragma unroll
                for (int r = 0; r < 4; r++) sacc[nt][r] = 0.f;
#pragma unroll
            for (int nt = 0; nt < 4; nt++) {
                const uint32_t nb = (uint32_t)((32 * wn + 8 * nt) * 144) + browB + bcolB;
#pragma unroll
                for (int ks = 0; ks < 4; ks++) {
                    uint32_t BH[2], BL[2];
                    ldmB(BH, sb + SKH + nb + ks * 32);
                    ldmB(BL, sb + SKL + nb + ks * 32);
                    mmabf(sacc[nt], AH[ks], BH);
                    mmabf(sacc[nt], AH[ks], BL);
                    mmabf(sacc[nt], AL[ks], BH);
                }
            }
            const int s0 = 64 * (h & 1);
            const int s1 = 64 * ((h + 1) & 1);
            const bool diag = (h == 0);
#pragma unroll
            for (int nt = 0; nt < 4; nt++) {
                const int klocal = 32 * wn + 8 * nt + 2 * (lane & 3);
                const int kg = k0 + klocal;
#pragma unroll
                for (int rh = 0; rh < 2; rh++) {
                    const int r = 16 * wm + 8 * rh + (lane >> 2);
                    const int qg = q0 + r;
                    const int d0 = r - klocal;
                    const int d1 = d0 - 1;
                    float r0 = Rs[r * SRSP + ((d0 & 63) + (d0 >= 0 ? s0 : s1))];
                    float r1 = Rs[r * SRSP + ((d1 & 63) + (d1 >= 0 ? s0 : s1))];
                    float sv0 = (sacc[nt][2 * rh] + r0) * 0.125f;
                    float sv1 = (sacc[nt][2 * rh + 1] + r1) * 0.125f;
                    float p0 = __expf(sv0), p1 = __expf(sv1);
                    if (diag) {
                        if (kg > qg) p0 = 0.f;
                        if (kg + 1 > qg) p1 = 0.f;
                    }
                    zacc[rh] += p0 + p1;
                    *((float2*)(attng + (size_t)qg * LSEQ + kg)) = make_float2(p0, p1);
                }
            }
        }

        // z reduce -> smem iz
#pragma unroll
        for (int rh = 0; rh < 2; rh++) {
            float v = zacc[rh];
            v += __shfl_xor_sync(0xffffffffu, v, 1);
            v += __shfl_xor_sync(0xffffffffu, v, 2);
            zacc[rh] = v;
        }
        __syncthreads();
        float* zb = Rs;
        if ((lane & 3) == 0) {
#pragma unroll
            for (int rh = 0; rh < 2; rh++) {
                int row = 16 * wm + 8 * rh + (lane >> 2);
                zb[row * 2 + wn] = zacc[rh];
            }
        }
        __syncthreads();
        if (t < 64)
            smIZ[t] = 1.f / (zb[2 * t] + zb[2 * t + 1]);
        __syncthreads();   // iz visible; score's attn writes visible block-wide
    }

    // ================= Phase 2: normalize + PV (R14 winner) =================
    {
        float cacc[4][4];
#pragma unroll
        for (int nt = 0; nt < 4; nt++)
#pragma unroll
            for (int r = 0; r < 4; r++) cacc[nt][r] = 0.f;

        const int arow = (lane & 7) + 8 * ((lane >> 3) & 1);
        const int acolB = 16 * (lane >> 4);
        const int btrow = (lane & 15) * 144;
        const int bncol = (32 * wn) * 2;

        const int vr = t >> 4, vc4 = t & 15;
        const int pr = t >> 5, pc4 = t & 31;

        const int kcov = (qt + 1) * 64;
        const int ktmax = qt >> 1;
        for (int kt = 0; kt <= ktmax; kt++) {
            const int k0 = kt * 128;
            const bool oob = (k0 + 4 * pc4) >= kcov;
            __syncthreads();

            float4 vbuf[8];
#pragma unroll
            for (int jj = 0; jj < 8; jj++)
                vbuf[jj] = *((const float4*)(Vg + (size_t)(k0 + vr + 16 * jj) * 64 + 4 * vc4));
#pragma unroll
            for (int jj = 0; jj < 8; jj++)
                split72(sm + PVH, sm + PVL, vr + 16 * jj, vc4, vbuf[jj]);

            float4 pbuf[8];
#pragma unroll
            for (int jj = 0; jj < 8; jj++)
                pbuf[jj] = *((const float4*)(attng +
                    (size_t)(q0 + pr + 8 * jj) * LSEQ + k0 + 4 * pc4));
#pragma unroll
            for (int jj = 0; jj < 8; jj++) {
                int r = pr + 8 * jj;
                float iz = smIZ[r];
                float4 pv = pbuf[jj];
                pv.x *= iz; pv.y *= iz; pv.z *= iz; pv.w *= iz;
                if (oob) pv = make_float4(0.f, 0.f, 0.f, 0.f);
                *((float4*)(attng + (size_t)(q0 + r) * LSEQ + k0 + 4 * pc4)) = pv;
                split136(sm + PPH, sm + PPL, r, pc4, pv);
            }
            __syncthreads();

#pragma unroll 2
            for (int ks = 0; ks < 8; ks++) {
                uint32_t PH[4], PL[4];
                {
                    uint32_t ro = (uint32_t)((16 * wm + arow) * 272 + ks * 32 + acolB);
                    ldmA(PH, sb + PPH + ro);
                    ldmA(PL, sb + PPL + ro);
                }
#pragma unroll
                for (int nt = 0; nt < 4; nt++) {
                    uint32_t BH[2], BL[2];
                    uint32_t bo = (uint32_t)(16 * ks * 144) + btrow + bncol + nt * 16;
                    ldmBT(BH, sb + PVH + bo);
                    ldmBT(BL, sb + PVL + bo);
                    mmabf(cacc[nt], PH, BH);
                    mmabf(cacc[nt], PH, BL);
                    mmabf(cacc[nt], PL, BH);
                }
            }
        }

        const int kend = (ktmax + 1) * 128;
        const int nz = (LSEQ - kend) >> 2;
        if (nz > 0) {
            const float4 z4 = make_float4(0.f, 0.f, 0.f, 0.f);
            for (int i = t; i < 64 * nz; i += 256) {
                int r = i / nz, c = i - r * nz;
                *((float4*)(attng + (size_t)(q0 + r) * LSEQ + kend + 4 * c)) = z4;
            }
        }

#pragma unroll
        for (int nt = 0; nt < 4; nt++)
#pragma unroll
            for (int rh = 0; rh < 2; rh++) {
                int q = q0 + 16 * wm + 8 * rh + (lane >> 2);
                int d = 32 * wn + 8 * nt + 2 * (lane & 3);
                *((float2*)(ctxg + (size_t)q * 64 + d)) =
                    make_float2(cacc[nt][2 * rh], cacc[nt][2 * rh + 1]);
            }
    }
}

extern "C" void kernel_launch(void* const* d_in, const int* in_sizes, int n_in,
                              void* d_out, int out_size) {
    const float* Q  = (const float*)d_in[0];
    const float* K  = (const float*)d_in[1];
    const float* V  = (const float*)d_in[2];
    const float* Er = (const float*)d_in[4];

    const long long CTXN = (long long)2 * 16 * 2048 * 64;
    const long long ATTN = (long long)2 * 16 * 2048 * 2048;
    float* out = (float*)d_out;
    float* ctx; float* attn;
    if ((long long)out_size >= CTXN + ATTN) { ctx = out; attn = out + CTXN; }
    else if ((long long)out_size == ATTN)   { ctx = nullptr; attn = out; }
    else                                    { ctx = out; attn = out; }

    cudaFuncSetAttribute(fused_attn, cudaFuncAttributeMaxDynamicSharedMemorySize, SMEM_F);
    fused_attn<<<dim3(32, 32), 256, SMEM_F>>>(Q, K, Er, V, ctx, attn);
}

// round 16
// speedup vs baseline: 1.3356x; 1.0097x over previous
#include <cuda_runtime.h>
#include <cuda_bf16.h>
#include <cstdint>

#define LSEQ 2048
typedef unsigned long long ull;

__device__ float g_ctx_scratch[2 * 16 * 2048 * 64];
// pre-split bf16 operands: each uint2 = 4 bf16 (cols 4c..4c+3)
__device__ uint2 g_Khi[32 * 2048 * 16];
__device__ uint2 g_Klo[32 * 2048 * 16];
__device__ uint2 g_Vhi[32 * 2048 * 16];
__device__ uint2 g_Vlo[32 * 2048 * 16];
__device__ uint2 g_Ehi[2048 * 16];        // row j = Er[2047 - j]
__device__ uint2 g_Elo[2048 * 16];

__device__ __forceinline__ uint32_t smem_u32(const void* p) {
    uint32_t a;
    asm("{ .reg .u64 t; cvta.to.shared.u64 t, %1; cvt.u32.u64 %0, t; }" : "=r"(a) : "l"(p));
    return a;
}
__device__ __forceinline__ void ldmA(uint32_t* a, uint32_t addr) {
    asm volatile("ldmatrix.sync.aligned.m8n8.x4.shared.b16 {%0,%1,%2,%3}, [%4];"
        : "=r"(a[0]), "=r"(a[1]), "=r"(a[2]), "=r"(a[3]) : "r"(addr));
}
__device__ __forceinline__ void ldmT4(uint32_t* a, uint32_t addr) {
    asm volatile("ldmatrix.sync.aligned.m8n8.x4.trans.shared.b16 {%0,%1,%2,%3}, [%4];"
        : "=r"(a[0]), "=r"(a[1]), "=r"(a[2]), "=r"(a[3]) : "r"(addr));
}
__device__ __forceinline__ void mmabf(float* d, const uint32_t* a, const uint32_t* b) {
    asm volatile("mma.sync.aligned.m16n8k16.row.col.f32.bf16.bf16.f32 "
        "{%0,%1,%2,%3}, {%4,%5,%6,%7}, {%8,%9}, {%0,%1,%2,%3};"
        : "+f"(d[0]), "+f"(d[1]), "+f"(d[2]), "+f"(d[3])
        : "r"(a[0]), "r"(a[1]), "r"(a[2]), "r"(a[3]), "r"(b[0]), "r"(b[1]));
}
__device__ __forceinline__ uint32_t pkbf(float a, float b) {
    __nv_bfloat162 h = __floats2bfloat162_rn(a, b);
    return *(uint32_t*)&h;
}
__device__ __forceinline__ void split72(char* hi, char* lo, int r, int c4, float4 v) {
    float hx = __bfloat162float(__float2bfloat16(v.x));
    float hy = __bfloat162float(__float2bfloat16(v.y));
    float hz = __bfloat162float(__float2bfloat16(v.z));
    float hw = __bfloat162float(__float2bfloat16(v.w));
    int off = r * 144 + c4 * 8;
    *(uint2*)(hi + off) = make_uint2(pkbf(v.x, v.y), pkbf(v.z, v.w));
    *(uint2*)(lo + off) = make_uint2(pkbf(v.x - hx, v.y - hy), pkbf(v.z - hz, v.w - hw));
}
__device__ __forceinline__ void split136(char* hi, char* lo, int r, int c4, float4 v) {
    float hx = __bfloat162float(__float2bfloat16(v.x));
    float hy = __bfloat162float(__float2bfloat16(v.y));
    float hz = __bfloat162float(__float2bfloat16(v.z));
    float hw = __bfloat162float(__float2bfloat16(v.w));
    int off = r * 272 + c4 * 8;
    *(uint2*)(hi + off) = make_uint2(pkbf(v.x, v.y), pkbf(v.z, v.w));
    *(uint2*)(lo + off) = make_uint2(pkbf(v.x - hx, v.y - hy), pkbf(v.z - hz, v.w - hw));
}

// ========== prep: split K/V/Er into global bf16 hi/lo (E row-reversed) =====
__global__ void prep_split(const float* __restrict__ K, const float* __restrict__ V,
                           const float* __restrict__ Er)
{
    const int m = blockIdx.x;                 // 0..31 K, 32..63 V, 64 E
    const int r0 = blockIdx.y * 64;
    const float* src;
    uint2 *dhi, *dlo;
    if (m < 32)      { src = K + (size_t)m * 2048 * 64;        dhi = g_Khi + (size_t)m * 2048 * 16; dlo = g_Klo + (size_t)m * 2048 * 16; }
    else if (m < 64) { src = V + (size_t)(m - 32) * 2048 * 64; dhi = g_Vhi + (size_t)(m - 32) * 2048 * 16; dlo = g_Vlo + (size_t)(m - 32) * 2048 * 16; }
    else             { src = Er;                                dhi = g_Ehi; dlo = g_Elo; }

    for (int i = threadIdx.x; i < 1024; i += 256) {
        int r = r0 + (i >> 4), c4 = i & 15;
        int sr = (m == 64) ? (2047 - r) : r;
        float4 v = *((const float4*)(src + (size_t)sr * 64 + 4 * c4));
        float hx = __bfloat162float(__float2bfloat16(v.x));
        float hy = __bfloat162float(__float2bfloat16(v.y));
        float hz = __bfloat162float(__float2bfloat16(v.z));
        float hw = __bfloat162float(__float2bfloat16(v.w));
        dhi[(size_t)r * 16 + c4] = make_uint2(pkbf(v.x, v.y), pkbf(v.z, v.w));
        dlo[(size_t)r * 16 + c4] =
            make_uint2(pkbf(v.x - hx, v.y - hy), pkbf(v.z - hz, v.w - hw));
    }
}

// ---- time-shared smem layout (same as R15) ----
#define SKH 0
#define SKL 9216
#define SEH 18432
#define SEL 27648
#define SRS 36864
#define SRSP 132
#define PPH 0
#define PPL 17408
#define PVH 34816
#define PVL 53248
#define OIZ 71680
#define SMEM_F 71936

__global__ void __launch_bounds__(256, 2)
fused_attn(const float* __restrict__ Q, float* __restrict__ ctx, float* __restrict__ attn)
{
    extern __shared__ char sm[];
    const uint32_t sb = smem_u32(sm);
    float* Rs = (float*)(sm + SRS);
    float* smIZ = (float*)(sm + OIZ);

    const int qt = 31 - (int)blockIdx.x;
    const int bh = blockIdx.y;
    const int q0 = qt * 64;
    const int t = threadIdx.x;
    const int wid = t >> 5, lane = t & 31;
    const int wm = wid >> 1;
    const int wn = wid & 1;

    if (ctx == nullptr) ctx = g_ctx_scratch;
    const float* Qg = Q + (size_t)bh * LSEQ * 64;
    float* attng = attn + (size_t)bh * LSEQ * LSEQ;
    float* ctxg = ctx + (size_t)bh * LSEQ * 64;
    const uint2* Khi = g_Khi + (size_t)bh * 2048 * 16;
    const uint2* Klo = g_Klo + (size_t)bh * 2048 * 16;
    const uint2* Vhi = g_Vhi + (size_t)bh * 2048 * 16;
    const uint2* Vlo = g_Vlo + (size_t)bh * 2048 * 16;

    const int lr = t >> 4, lc4 = t & 15;

    // ================= Phase 1: scores =================
    {
        for (int i = t; i < 1024; i += 256) {
            int r = i >> 4, c4 = i & 15;
            split72(sm + SRS, sm + SRS + 9216, r, c4,
                    *((const float4*)(Qg + (size_t)(q0 + r) * 64 + 4 * c4)));
        }
        __syncthreads();

        const int arow = (lane & 7) + 8 * ((lane >> 3) & 1);
        const int acolB = 16 * (lane >> 4);
        uint32_t AH[4][4], AL[4][4];
#pragma unroll
        for (int ks = 0; ks < 4; ks++) {
            uint32_t ro = (uint32_t)((16 * wm + arow) * 144 + ks * 32 + acolB);
            ldmA(AH[ks], sb + SRS + ro);
            ldmA(AL[ks], sb + SRS + 9216 + ro);
        }

        // x4 B addressing: 16 rows per load
        const int browB4 = ((lane & 7) + 8 * (lane >> 4)) * 144;
        const int bcolB = 16 * ((lane >> 3) & 1);
        float zacc[2] = {0.f, 0.f};

        uint2 kh[4], kl[4], eh[4], el[4];
        {
            const int k0 = qt * 64;
#pragma unroll
            for (int jj = 0; jj < 4; jj++) {
                size_t ki = (size_t)(k0 + lr + 16 * jj) * 16 + lc4;
                kh[jj] = Khi[ki]; kl[jj] = Klo[ki];
                size_t ei = (size_t)(lr + 16 * jj) * 16 + lc4;
                eh[jj] = g_Ehi[ei]; el[jj] = g_Elo[ei];
            }
        }

        for (int h = 0; h <= qt; h++) {
            const int k0 = (qt - h) * 64;
            __syncthreads();

#pragma unroll
            for (int jj = 0; jj < 4; jj++) {
                int off = (lr + 16 * jj) * 144 + lc4 * 8;
                *(uint2*)(sm + SKH + off) = kh[jj];
                *(uint2*)(sm + SKL + off) = kl[jj];
                *(uint2*)(sm + SEH + off) = eh[jj];
                *(uint2*)(sm + SEL + off) = el[jj];
            }

            if (h < qt) {
                const int k0n = (qt - h - 1) * 64;
                const int e0n = 64 * (h + 1);
#pragma unroll
                for (int jj = 0; jj < 4; jj++) {
                    size_t ki = (size_t)(k0n + lr + 16 * jj) * 16 + lc4;
                    kh[jj] = Khi[ki]; kl[jj] = Klo[ki];
                    size_t ei = (size_t)(e0n + lr + 16 * jj) * 16 + lc4;
                    eh[jj] = g_Ehi[ei]; el[jj] = g_Elo[ei];
                }
            }
            __syncthreads();

            // ---- R phase (x4 B loads) ----
            const int slotW = 64 * (h & 1);
#pragma unroll
            for (int ntp = 0; ntp < 2; ntp++) {
                float racc0[4] = {0.f, 0.f, 0.f, 0.f};
                float racc1[4] = {0.f, 0.f, 0.f, 0.f};
                const uint32_t nb = (uint32_t)((32 * wn + 16 * ntp) * 144) + browB4 + bcolB;
#pragma unroll
                for (int ks = 0; ks < 4; ks++) {
                    uint32_t BH[4], BL[4];
                    ldmA(BH, sb + SEH + nb + ks * 32);
                    ldmA(BL, sb + SEL + nb + ks * 32);
                    mmabf(racc0, AH[ks], BH);
                    mmabf(racc0, AH[ks], BL);
                    mmabf(racc0, AL[ks], BH);
                    mmabf(racc1, AH[ks], BH + 2);
                    mmabf(racc1, AH[ks], BL + 2);
                    mmabf(racc1, AL[ks], BH + 2);
                }
                const int q = 16 * wm + (lane >> 2);
                const int c0 = slotW + 32 * wn + 16 * ntp + 2 * (lane & 3);
#pragma unroll
                for (int half = 0; half < 2; half++) {
                    float* dst = Rs + (q + 8 * half) * SRSP;
                    *((float2*)(dst + c0))     = make_float2(racc0[2 * half], racc0[2 * half + 1]);
                    *((float2*)(dst + c0 + 8)) = make_float2(racc1[2 * half], racc1[2 * half + 1]);
                }
            }
            __syncthreads();

            // ---- S MMA (x4 B loads) + epilogue ----
            float sacc[4][4];
#pragma unroll
            for (int nt = 0; nt < 4; nt++)
#pragma unroll
                for (int r = 0; r < 4; r++) sacc[nt][r] = 0.f;
#pragma unroll
            for (int ntp = 0; ntp < 2; ntp++) {
                const uint32_t nb = (uint32_t)((32 * wn + 16 * ntp) * 144) + browB4 + bcolB;
#pragma unroll
                for (int ks = 0; ks < 4; ks++) {
                    uint32_t BH[4], BL[4];
                    ldmA(BH, sb + SKH + nb + ks * 32);
                    ldmA(BL, sb + SKL + nb + ks * 32);
                    mmabf(sacc[2 * ntp], AH[ks], BH);
                    mmabf(sacc[2 * ntp], AH[ks], BL);
                    mmabf(sacc[2 * ntp], AL[ks], BH);
                    mmabf(sacc[2 * ntp + 1], AH[ks], BH + 2);
                    mmabf(sacc[2 * ntp + 1], AH[ks], BL + 2);
                    mmabf(sacc[2 * ntp + 1], AL[ks], BH + 2);
                }
            }
            const int s0 = 64 * (h & 1);
            const int s1 = 64 * ((h + 1) & 1);
            const bool diag = (h == 0);
#pragma unroll
            for (int nt = 0; nt < 4; nt++) {
                const int klocal = 32 * wn + ((nt & 1) ? 8 : 0) + 16 * (nt >> 1) + 2 * (lane & 3);
                const int kg = k0 + klocal;
#pragma unroll
                for (int rh = 0; rh < 2; rh++) {
                    const int r = 16 * wm + 8 * rh + (lane >> 2);
                    const int qg = q0 + r;
                    const int d0 = r - klocal;
                    const int d1 = d0 - 1;
                    float r0 = Rs[r * SRSP + ((d0 & 63) + (d0 >= 0 ? s0 : s1))];
                    float r1 = Rs[r * SRSP + ((d1 & 63) + (d1 >= 0 ? s0 : s1))];
                    // sacc index: nt order is [2*ntp], [2*ntp+1] with cols 16*ntp, 16*ntp+8
                    const int si = (nt >> 1) * 2 + (nt & 1);
                    float sv0 = (sacc[si][2 * rh] + r0) * 0.125f;
                    float sv1 = (sacc[si][2 * rh + 1] + r1) * 0.125f;
                    float p0 = __expf(sv0), p1 = __expf(sv1);
                    if (diag) {
                        if (kg > qg) p0 = 0.f;
                        if (kg + 1 > qg) p1 = 0.f;
                    }
                    zacc[rh] += p0 + p1;
                    *((float2*)(attng + (size_t)qg * LSEQ + kg)) = make_float2(p0, p1);
                }
            }
        }

        // z reduce -> smem iz
#pragma unroll
        for (int rh = 0; rh < 2; rh++) {
            float v = zacc[rh];
            v += __shfl_xor_sync(0xffffffffu, v, 1);
            v += __shfl_xor_sync(0xffffffffu, v, 2);
            zacc[rh] = v;
        }
        __syncthreads();
        float* zb = Rs;
        if ((lane & 3) == 0) {
#pragma unroll
            for (int rh = 0; rh < 2; rh++) {
                int row = 16 * wm + 8 * rh + (lane >> 2);
                zb[row * 2 + wn] = zacc[rh];
            }
        }
        __syncthreads();
        if (t < 64)
            smIZ[t] = 1.f / (zb[2 * t] + zb[2 * t + 1]);
        __syncthreads();
    }

    // ================= Phase 2: normalize + PV =================
    {
        float cacc[4][4];
#pragma unroll
        for (int nt = 0; nt < 4; nt++)
#pragma unroll
            for (int r = 0; r < 4; r++) cacc[nt][r] = 0.f;

        const int arow = (lane & 7) + 8 * ((lane >> 3) & 1);
        const int acolB = 16 * (lane >> 4);
        const int btrow4 = (lane & 15) * 144 + (lane >> 4) * 16;
        const int bncol = (32 * wn) * 2;

        const int vr = t >> 4, vc4 = t & 15;
        const int pr = t >> 5, pc4 = t & 31;

        const int kcov = (qt + 1) * 64;
        const int ktmax = qt >> 1;
        for (int kt = 0; kt <= ktmax; kt++) {
            const int k0 = kt * 128;
            const bool oob = (k0 + 4 * pc4) >= kcov;
            __syncthreads();

            uint2 vh[8], vl[8];
#pragma unroll
            for (int jj = 0; jj < 8; jj++) {
                size_t vi = (size_t)(k0 + vr + 16 * jj) * 16 + vc4;
                vh[jj] = Vhi[vi]; vl[jj] = Vlo[vi];
            }
#pragma unroll
            for (int jj = 0; jj < 8; jj++) {
                int off = (vr + 16 * jj) * 144 + vc4 * 8;
                *(uint2*)(sm + PVH + off) = vh[jj];
                *(uint2*)(sm + PVL + off) = vl[jj];
            }

            float4 pbuf[8];
#pragma unroll
            for (int jj = 0; jj < 8; jj++)
                pbuf[jj] = *((const float4*)(attng +
                    (size_t)(q0 + pr + 8 * jj) * LSEQ + k0 + 4 * pc4));
#pragma unroll
            for (int jj = 0; jj < 8; jj++) {
                int r = pr + 8 * jj;
                float iz = smIZ[r];
                float4 pv = pbuf[jj];
                pv.x *= iz; pv.y *= iz; pv.z *= iz; pv.w *= iz;
                if (oob) pv = make_float4(0.f, 0.f, 0.f, 0.f);
                *((float4*)(attng + (size_t)(q0 + r) * LSEQ + k0 + 4 * pc4)) = pv;
                split136(sm + PPH, sm + PPL, r, pc4, pv);
            }
            __syncthreads();

#pragma unroll 2
            for (int ks = 0; ks < 8; ks++) {
                uint32_t PH[4], PL[4];
                {
                    uint32_t ro = (uint32_t)((16 * wm + arow) * 272 + ks * 32 + acolB);
                    ldmA(PH, sb + PPH + ro);
                    ldmA(PL, sb + PPL + ro);
                }
#pragma unroll
                for (int ntp = 0; ntp < 2; ntp++) {
                    uint32_t BH[4], BL[4];
                    uint32_t bo = (uint32_t)(16 * ks * 144) + btrow4 + bncol + ntp * 32;
                    ldmT4(BH, sb + PVH + bo);
                    ldmT4(BL, sb + PVL + bo);
                    mmabf(cacc[2 * ntp], PH, BH);
                    mmabf(cacc[2 * ntp], PH, BL);
                    mmabf(cacc[2 * ntp], PL, BH);
                    mmabf(cacc[2 * ntp + 1], PH, BH + 2);
                    mmabf(cacc[2 * ntp + 1], PH, BL + 2);
                    mmabf(cacc[2 * ntp + 1], PL, BH + 2);
                }
            }
        }

        const int kend = (ktmax + 1) * 128;
        const int nz = (LSEQ - kend) >> 2;
        if (nz > 0) {
            const float4 z4 = make_float4(0.f, 0.f, 0.f, 0.f);
            for (int i = t; i < 64 * nz; i += 256) {
                int r = i / nz, c = i - r * nz;
                *((float4*)(attng + (size_t)(q0 + r) * LSEQ + kend + 4 * c)) = z4;
            }
        }

        // ctx epilogue; cacc[2*ntp(+1)] covers d = 32*wn + 16*ntp (+8)
#pragma unroll
        for (int nt = 0; nt < 4; nt++)
#pragma unroll
            for (int rh = 0; rh < 2; rh++) {
                int q = q0 + 16 * wm + 8 * rh + (lane >> 2);
                int d = 32 * wn + 16 * (nt >> 1) + 8 * (nt & 1) + 2 * (lane & 3);
                *((float2*)(ctxg + (size_t)q * 64 + d)) =
                    make_float2(cacc[nt][2 * rh], cacc[nt][2 * rh + 1]);
            }
    }
}

extern "C" void kernel_launch(void* const* d_in, const int* in_sizes, int n_in,
                              void* d_out, int out_size) {
    const float* Q  = (const float*)d_in[0];
    const float* K  = (const float*)d_in[1];
    const float* V  = (const float*)d_in[2];
    const float* Er = (const float*)d_in[4];

    const long long CTXN = (long long)2 * 16 * 2048 * 64;
    const long long ATTN = (long long)2 * 16 * 2048 * 2048;
    float* out = (float*)d_out;
    float* ctx; float* attn;
    if ((long long)out_size >= CTXN + ATTN) { ctx = out; attn = out + CTXN; }
    else if ((long long)out_size == ATTN)   { ctx = nullptr; attn = out; }
    else                                    { ctx = out; attn = out; }

    prep_split<<<dim3(65, 32), 256>>>(K, V, Er);

    cudaFuncSetAttribute(fused_attn, cudaFuncAttributeMaxDynamicSharedMemorySize, SMEM_F);
    fused_attn<<<dim3(32, 32), 256, SMEM_F>>>(Q, ctx, attn);
}